// round 7
// baseline (speedup 1.0000x reference)
#include <cuda_runtime.h>
#include <cuda_bf16.h>
#include <math.h>

#define N_GAUSS 2048
#define HEIGHT  192
#define WIDTH   192
#define HW      (HEIGHT*WIDTH)
#define ALPHA_MAX 0.999f
#define ALPHA_MIN (1.0f/255.0f)
#define NSEG    8
#define SEG     (N_GAUSS / NSEG)   // 256
#define NTILE   144                // 12x12 tiles

// Depth-sorted gaussian data
__device__ float4 g_A[N_GAUSS];  // mx, my, conic_a, conic_b
__device__ float4 g_B[N_GAUSS];  // conic_c, opacity, col_r, col_g
__device__ float2 g_C[N_GAUSS];  // col_b, sigma_threshold = log(255*op)+margin
__device__ float2 g_D[N_GAUSS];  // rx, ry : AABB half-extents
// Per-segment partial composites: (accR, accG, accB, T_seg)
__device__ float4 g_seg[NSEG][HW];
// Per-tile completion counters (reset by sort kernel every launch)
__device__ int g_tilecnt[NTILE];

// ---------------------------------------------------------------------------
// Kernel 1: rank-by-counting sort fused with param scatter. Param loads are
// hoisted ABOVE the count loop so their global latency overlaps counting.
// Also resets the per-tile fold counters for this run.
// ---------------------------------------------------------------------------
__global__ void __launch_bounds__(256)
sort_scatter_kernel(const float* __restrict__ means2d,
                    const float* __restrict__ conics,
                    const float* __restrict__ colors,
                    const float* __restrict__ opacities,
                    const float* __restrict__ depths)
{
    __shared__ unsigned long long keys[N_GAUSS];
    __shared__ int cnt[16][17];
    const int tid = threadIdx.x;

    if (blockIdx.x == 0 && tid < NTILE) g_tilecnt[tid] = 0;

    // Early param loads for this block's 16 gaussians (independent of ranks;
    // latency overlaps key staging + counting below).
    float p_mx, p_my, p_ca, p_cb, p_cc, p_op, p_cr, p_cg, p_cbl;
    if (tid < 16) {
        int src = blockIdx.x * 16 + tid;
        p_mx = means2d[2*src + 0];
        p_my = means2d[2*src + 1];
        p_ca = conics[3*src + 0];
        p_cb = conics[3*src + 1];
        p_cc = conics[3*src + 2];
        p_op = opacities[src];
        p_cr = colors[3*src + 0];
        p_cg = colors[3*src + 1];
        p_cbl= colors[3*src + 2];
    }

    // (depth_bits << 32) | index : depths > 0 so float bits order like floats.
    #pragma unroll
    for (int i = tid; i < N_GAUSS; i += 256)
        keys[i] = (((unsigned long long)__float_as_uint(depths[i])) << 32) | (unsigned)i;
    __syncthreads();

    const int gl    = tid & 15;
    const int slice = tid >> 4;
    const unsigned long long mykey = keys[blockIdx.x * 16 + gl];

    int c = 0;
    const int s0 = slice * (N_GAUSS / 16);
    #pragma unroll 8
    for (int i = 0; i < N_GAUSS / 16; ++i)
        c += (keys[s0 + i] < mykey);
    cnt[slice][gl] = c;
    __syncthreads();

    if (tid < 16) {
        int rank = 0;
        #pragma unroll
        for (int s = 0; s < 16; ++s) rank += cnt[s][tid];
        // alpha >= 1/255  <=>  sigma <= log(255*op); +margin keeps the cheap
        // reject conservative vs the exact in-branch check.
        float t = logf(255.0f * p_op) + 1e-4f;
        float det = p_ca * p_cc - p_cb * p_cb;
        float inv = 2.0f * fmaxf(t, 0.0f) / det;
        float rx = sqrtf(fmaxf(inv * p_cc, 0.0f)) + 1e-3f;
        float ry = sqrtf(fmaxf(inv * p_ca, 0.0f)) + 1e-3f;
        g_A[rank] = make_float4(p_mx, p_my, p_ca, p_cb);
        g_B[rank] = make_float4(p_cc, p_op, p_cr, p_cg);
        g_C[rank] = make_float2(p_cbl, t);
        g_D[rank] = make_float2(rx, ry);
    }
}

// ---------------------------------------------------------------------------
// Kernel 2: depth-segmented, per-warp strip-culled compositing with fused
// final fold. grid (12,12,NSEG); block z composites gaussians
// [z*SEG,(z+1)*SEG) for one 16x16 tile and writes (accRGB, T_seg). The LAST
// block to finish a tile folds all NSEG segments + background into out.
// ---------------------------------------------------------------------------
__global__ void __launch_bounds__(256)
render_seg_kernel(const float* __restrict__ background, float* __restrict__ out)
{
    __shared__ float4 sA[SEG];
    __shared__ float4 sB[SEG];
    __shared__ float2 sC[SEG];
    __shared__ float2 sD[SEG];
    __shared__ bool amLast;

    const int tid  = threadIdx.x;
    const int warp = tid >> 5, lane = tid & 31;
    const int seg  = blockIdx.z;
    const int base = seg * SEG;
    const int x = blockIdx.x * 16 + (tid & 15);
    const int y = blockIdx.y * 16 + (tid >> 4);
    const int pix = y * WIDTH + x;
    const float px = (float)x + 0.5f;
    const float py = (float)y + 0.5f;

    const float sxmin = blockIdx.x * 16 + 0.5f;
    const float sxmax = blockIdx.x * 16 + 15.5f;
    const float symin = blockIdx.y * 16 + 2 * warp + 0.5f;
    const float symax = symin + 1.0f;

    #pragma unroll
    for (int k = 0; k < SEG / 256; ++k) {
        int i = tid + k * 256;
        sA[i] = g_A[base + i];
        sB[i] = g_B[base + i];
        sC[i] = g_C[base + i];
        sD[i] = g_D[base + i];
    }
    __syncthreads();

    float T = 1.0f;
    float accr = 0.0f, accg = 0.0f, accb = 0.0f;

    for (int g = 0; g < SEG; g += 32) {
        // Lane-parallel cull of this 32-group against the warp's 16x2 strip.
        float4 a = sA[g + lane];
        float2 r = sD[g + lane];
        bool pred = (a.x - r.x <= sxmax) & (a.x + r.x >= sxmin) &
                    (a.y - r.y <= symax) & (a.y + r.y >= symin);
        unsigned mask = __ballot_sync(0xffffffffu, pred);

        // 2-wide in-order walk over survivors (paired loads/sigma/exp = ILP;
        // T-chain stays exactly ordered).
        while (mask) {
            int j0 = g + (__ffs(mask) - 1);
            mask &= mask - 1;
            bool two = (mask != 0);
            int j1 = two ? (g + (__ffs(mask) - 1)) : j0;
            if (two) mask &= mask - 1;

            float4 A0 = sA[j0], A1 = sA[j1];
            float4 B0 = sB[j0], B1 = sB[j1];
            float2 C0 = sC[j0], C1 = sC[j1];

            float dx0 = px - A0.x, dy0 = py - A0.y;
            float dx1 = px - A1.x, dy1 = py - A1.y;
            float sg0 = 0.5f * (A0.z*dx0*dx0 + B0.x*dy0*dy0) + A0.w*dx0*dy0;
            float sg1 = 0.5f * (A1.z*dx1*dx1 + B1.x*dy1*dy1) + A1.w*dx1*dy1;
            float e0 = __expf(-sg0);
            float e1 = __expf(-sg1);

            if (sg0 > 0.0f && sg0 < C0.y) {
                float alpha = fminf(ALPHA_MAX, B0.y * e0);
                if (alpha >= ALPHA_MIN) {          // exact reference condition
                    float w = T * alpha;
                    accr = fmaf(w, B0.z, accr);
                    accg = fmaf(w, B0.w, accg);
                    accb = fmaf(w, C0.x, accb);
                    T *= (1.0f - alpha);
                }
            }
            if (two && sg1 > 0.0f && sg1 < C1.y) {
                float alpha = fminf(ALPHA_MAX, B1.y * e1);
                if (alpha >= ALPHA_MIN) {
                    float w = T * alpha;
                    accr = fmaf(w, B1.z, accr);
                    accg = fmaf(w, B1.w, accg);
                    accb = fmaf(w, C1.x, accb);
                    T *= (1.0f - alpha);
                }
            }
        }
        // Segment-local early exit: dropped contributions bounded by
        // prefixT(<=1) * T_seg < 1e-7 absolute.
        if (!__ballot_sync(0xffffffffu, T >= 1e-7f)) break;
    }

    g_seg[seg][pix] = make_float4(accr, accg, accb, T);

    // --- last-block-folds protocol (threadFenceReduction pattern) ---
    __threadfence();                 // make this thread's store visible (gpu scope)
    __syncthreads();                 // all threads of this block fenced
    if (tid == 0) {
        int t = atomicAdd(&g_tilecnt[blockIdx.y * 12 + blockIdx.x], 1);
        amLast = (t == NSEG - 1);
    }
    __syncthreads();
    if (amLast) {
        __threadfence();             // acquire side: order fold loads after counter
        float fr = 0.0f, fg = 0.0f, fb = 0.0f, fT = 1.0f;
        #pragma unroll
        for (int s = 0; s < NSEG; ++s) {
            float4 v = g_seg[s][pix];
            fr = fmaf(fT, v.x, fr);
            fg = fmaf(fT, v.y, fg);
            fb = fmaf(fT, v.z, fb);
            fT *= v.w;
        }
        out[0 * HW + pix] = fmaf(background[0], fT, fr);
        out[1 * HW + pix] = fmaf(background[1], fT, fg);
        out[2 * HW + pix] = fmaf(background[2], fT, fb);
    }
}

// ---------------------------------------------------------------------------
extern "C" void kernel_launch(void* const* d_in, const int* in_sizes, int n_in,
                              void* d_out, int out_size)
{
    const float* means2d    = (const float*)d_in[0];
    const float* conics     = (const float*)d_in[1];
    const float* colors     = (const float*)d_in[2];
    const float* opacities  = (const float*)d_in[3];
    const float* depths     = (const float*)d_in[4];
    const float* background = (const float*)d_in[5];
    float* out = (float*)d_out;

    sort_scatter_kernel<<<128, 256>>>(means2d, conics, colors, opacities, depths);
    dim3 grid(WIDTH / 16, HEIGHT / 16, NSEG);
    render_seg_kernel<<<grid, 256>>>(background, out);
}

// round 8
// speedup vs baseline: 1.0135x; 1.0135x over previous
#include <cuda_runtime.h>
#include <cuda_bf16.h>
#include <math.h>

#define N_GAUSS 2048
#define HEIGHT  192
#define WIDTH   192
#define HW      (HEIGHT*WIDTH)
#define ALPHA_MAX 0.999f
#define ALPHA_MIN (1.0f/255.0f)
#define NSEG    8
#define SEG     (N_GAUSS / NSEG)   // 256

// Depth-sorted gaussian data
__device__ float4 g_A[N_GAUSS];  // mx, my, conic_a, conic_b
__device__ float4 g_B[N_GAUSS];  // conic_c, opacity, col_r, col_g
__device__ float2 g_C[N_GAUSS];  // col_b, sigma_threshold = log(255*op)+margin
__device__ float2 g_D[N_GAUSS];  // rx, ry : AABB half-extents
// Per-segment partial composites: (accR, accG, accB, T_seg)
__device__ float4 g_seg[NSEG][HW];

// ---------------------------------------------------------------------------
// Kernel 1: rank-by-counting sort with 32-bit float keys. Order is
// lexicographic (depth, index); index == smem position, so ties resolve with
// the loop index. Param loads hoisted above counting to overlap latency.
// ---------------------------------------------------------------------------
__global__ void __launch_bounds__(256)
sort_scatter_kernel(const float* __restrict__ means2d,
                    const float* __restrict__ conics,
                    const float* __restrict__ colors,
                    const float* __restrict__ opacities,
                    const float* __restrict__ depths)
{
    __shared__ float sd[N_GAUSS];
    __shared__ int cnt[16][17];
    const int tid = threadIdx.x;

    // Early param loads for this block's 16 gaussians (rank-independent;
    // global latency overlaps key staging + counting).
    float p_mx, p_my, p_ca, p_cb, p_cc, p_op, p_cr, p_cg, p_cbl;
    if (tid < 16) {
        int src = blockIdx.x * 16 + tid;
        p_mx = means2d[2*src + 0];
        p_my = means2d[2*src + 1];
        p_ca = conics[3*src + 0];
        p_cb = conics[3*src + 1];
        p_cc = conics[3*src + 2];
        p_op = opacities[src];
        p_cr = colors[3*src + 0];
        p_cg = colors[3*src + 1];
        p_cbl= colors[3*src + 2];
    }

    #pragma unroll
    for (int i = tid; i < N_GAUSS; i += 256)
        sd[i] = depths[i];
    __syncthreads();

    const int gl    = tid & 15;
    const int slice = tid >> 4;
    const int gid   = blockIdx.x * 16 + gl;     // also this key's position
    const float myd = sd[gid];

    int c = 0;
    const int s0 = slice * (N_GAUSS / 16);
    #pragma unroll 8
    for (int k = 0; k < N_GAUSS / 16; ++k) {
        int i = s0 + k;
        float d = sd[i];
        c += (d < myd) || ((d == myd) && (i < gid));
    }
    cnt[slice][gl] = c;
    __syncthreads();

    if (tid < 16) {
        int rank = 0;
        #pragma unroll
        for (int s = 0; s < 16; ++s) rank += cnt[s][tid];
        // alpha >= 1/255  <=>  sigma <= log(255*op); +margin keeps the cheap
        // reject conservative vs the exact in-branch check.
        float t = logf(255.0f * p_op) + 1e-4f;
        float det = p_ca * p_cc - p_cb * p_cb;
        float inv = 2.0f * fmaxf(t, 0.0f) / det;
        float rx = sqrtf(fmaxf(inv * p_cc, 0.0f)) + 1e-3f;
        float ry = sqrtf(fmaxf(inv * p_ca, 0.0f)) + 1e-3f;
        g_A[rank] = make_float4(p_mx, p_my, p_ca, p_cb);
        g_B[rank] = make_float4(p_cc, p_op, p_cr, p_cg);
        g_C[rank] = make_float2(p_cbl, t);
        g_D[rank] = make_float2(rx, ry);
    }
}

// ---------------------------------------------------------------------------
// Kernel 2: depth-segmented, per-warp strip-culled compositing.
// grid (12,12,NSEG); block z composites gaussians [z*SEG,(z+1)*SEG) for one
// 16x16 tile and writes (accRGB, T_seg). No fences, no atomics -> gaussian
// data stays L1/smem resident.
// ---------------------------------------------------------------------------
__global__ void __launch_bounds__(256)
render_seg_kernel()
{
    __shared__ float4 sA[SEG];
    __shared__ float4 sB[SEG];
    __shared__ float2 sC[SEG];
    __shared__ float2 sD[SEG];

    const int tid  = threadIdx.x;
    const int warp = tid >> 5, lane = tid & 31;
    const int seg  = blockIdx.z;
    const int base = seg * SEG;
    const int x = blockIdx.x * 16 + (tid & 15);
    const int y = blockIdx.y * 16 + (tid >> 4);
    const float px = (float)x + 0.5f;
    const float py = (float)y + 0.5f;

    const float sxmin = blockIdx.x * 16 + 0.5f;
    const float sxmax = blockIdx.x * 16 + 15.5f;
    const float symin = blockIdx.y * 16 + 2 * warp + 0.5f;
    const float symax = symin + 1.0f;

    {
        int i = tid;               // SEG == 256: one record per thread
        sA[i] = g_A[base + i];
        sB[i] = g_B[base + i];
        sC[i] = g_C[base + i];
        sD[i] = g_D[base + i];
    }
    __syncthreads();

    float T = 1.0f;
    float accr = 0.0f, accg = 0.0f, accb = 0.0f;

    for (int g = 0; g < SEG; g += 32) {
        // Lane-parallel cull of this 32-group against the warp's 16x2 strip.
        float4 a = sA[g + lane];
        float2 r = sD[g + lane];
        bool pred = (a.x - r.x <= sxmax) & (a.x + r.x >= sxmin) &
                    (a.y - r.y <= symax) & (a.y + r.y >= symin);
        unsigned mask = __ballot_sync(0xffffffffu, pred);

        // 2-wide in-order walk over survivors (paired loads/sigma/exp = ILP;
        // T-chain stays exactly ordered).
        while (mask) {
            int j0 = g + (__ffs(mask) - 1);
            mask &= mask - 1;
            bool two = (mask != 0);
            int j1 = two ? (g + (__ffs(mask) - 1)) : j0;
            if (two) mask &= mask - 1;

            float4 A0 = sA[j0], A1 = sA[j1];
            float4 B0 = sB[j0], B1 = sB[j1];
            float2 C0 = sC[j0], C1 = sC[j1];

            float dx0 = px - A0.x, dy0 = py - A0.y;
            float dx1 = px - A1.x, dy1 = py - A1.y;
            float sg0 = 0.5f * (A0.z*dx0*dx0 + B0.x*dy0*dy0) + A0.w*dx0*dy0;
            float sg1 = 0.5f * (A1.z*dx1*dx1 + B1.x*dy1*dy1) + A1.w*dx1*dy1;
            float e0 = __expf(-sg0);
            float e1 = __expf(-sg1);

            if (sg0 > 0.0f && sg0 < C0.y) {
                float alpha = fminf(ALPHA_MAX, B0.y * e0);
                if (alpha >= ALPHA_MIN) {          // exact reference condition
                    float w = T * alpha;
                    accr = fmaf(w, B0.z, accr);
                    accg = fmaf(w, B0.w, accg);
                    accb = fmaf(w, C0.x, accb);
                    T *= (1.0f - alpha);
                }
            }
            if (two && sg1 > 0.0f && sg1 < C1.y) {
                float alpha = fminf(ALPHA_MAX, B1.y * e1);
                if (alpha >= ALPHA_MIN) {
                    float w = T * alpha;
                    accr = fmaf(w, B1.z, accr);
                    accg = fmaf(w, B1.w, accg);
                    accb = fmaf(w, C1.x, accb);
                    T *= (1.0f - alpha);
                }
            }
        }
        // Segment-local early exit: dropped contributions bounded by
        // prefixT(<=1) * T_seg < 1e-7 absolute.
        if (!__ballot_sync(0xffffffffu, T >= 1e-7f)) break;
    }

    g_seg[seg][y * WIDTH + x] = make_float4(accr, accg, accb, T);
}

// ---------------------------------------------------------------------------
// Kernel 3: fold segments front-to-back + background.
// ---------------------------------------------------------------------------
__global__ void __launch_bounds__(256)
combine_kernel(const float* __restrict__ background, float* __restrict__ out)
{
    const int pix = blockIdx.x * 256 + threadIdx.x;
    float accr = 0.0f, accg = 0.0f, accb = 0.0f, T = 1.0f;
    #pragma unroll
    for (int s = 0; s < NSEG; ++s) {
        float4 v = g_seg[s][pix];
        accr = fmaf(T, v.x, accr);
        accg = fmaf(T, v.y, accg);
        accb = fmaf(T, v.z, accb);
        T *= v.w;
    }
    out[0 * HW + pix] = fmaf(background[0], T, accr);
    out[1 * HW + pix] = fmaf(background[1], T, accg);
    out[2 * HW + pix] = fmaf(background[2], T, accb);
}

// ---------------------------------------------------------------------------
extern "C" void kernel_launch(void* const* d_in, const int* in_sizes, int n_in,
                              void* d_out, int out_size)
{
    const float* means2d    = (const float*)d_in[0];
    const float* conics     = (const float*)d_in[1];
    const float* colors     = (const float*)d_in[2];
    const float* opacities  = (const float*)d_in[3];
    const float* depths     = (const float*)d_in[4];
    const float* background = (const float*)d_in[5];
    float* out = (float*)d_out;

    sort_scatter_kernel<<<128, 256>>>(means2d, conics, colors, opacities, depths);
    dim3 grid(WIDTH / 16, HEIGHT / 16, NSEG);
    render_seg_kernel<<<grid, 256>>>();
    combine_kernel<<<HW / 256, 256>>>(background, out);
}